// round 4
// baseline (speedup 1.0000x reference)
#include <cuda_runtime.h>
#include <cstdint>
#include <cstddef>

#define B_    64
#define S_    256
#define H_    16
#define D_    256
#define HIDN  4096
#define M_    (B_*S_)          // 16384 tokens
#define JVALID 192             // S - WINDOW
#define SCALE_ 0.0625f         // 1/sqrt(256)

#define TS 132                 // smem tile stride (128 + 4 pad)

// Scratch: Q, K1, K2, V each laid out [b][h][s][d] (65536 floats per (b,h))
__device__ float g_scratch[(size_t)4 * M_ * HIDN];   // 1 GiB
__device__ float g_wv[(size_t)HIDN * HIDN];          // wv1 + wv2
__device__ float g_bv[HIDN];

// ---------------------------------------------------------------------------
// Kernel 0: combine V weights/bias (P@v1 + P@v2 == P@(v1+v2))
// ---------------------------------------------------------------------------
__global__ void combine_wv(const float* __restrict__ wv1, const float* __restrict__ wv2,
                           const float* __restrict__ bv1, const float* __restrict__ bv2) {
    size_t i = (size_t)blockIdx.x * blockDim.x + threadIdx.x;
    if (i < (size_t)HIDN * HIDN) g_wv[i] = wv1[i] + wv2[i];
    if (i < HIDN)                g_bv[i] = bv1[i] + bv2[i];
}

// ---------------------------------------------------------------------------
// Shared micro-GEMM helpers (128x128 tile, K-chunk 16, 256 threads, 8x8/thread)
// ---------------------------------------------------------------------------

// Load a [128 rows x 16 k] tile where k is the contiguous axis of src
// (row stride = ld), storing TRANSPOSED into Ts[k*TS + row].
__device__ __forceinline__ void load_tileT(float* Ts, const float* src, int ld, int tid) {
#pragma unroll
    for (int it = 0; it < 2; it++) {
        int idx = tid + it * 256;          // 512 float4s total
        int row = idx >> 2;
        int k4  = (idx & 3) << 2;
        float4 v = *(const float4*)(src + (size_t)row * ld + k4);
        Ts[(k4 + 0) * TS + row] = v.x;
        Ts[(k4 + 1) * TS + row] = v.y;
        Ts[(k4 + 2) * TS + row] = v.z;
        Ts[(k4 + 3) * TS + row] = v.w;
    }
}

// Load a [16 k x 128 n] tile where n is the contiguous axis of src
// (k-row stride = ld), storing into Ts[k*TS + n].
__device__ __forceinline__ void load_tileN(float* Ts, const float* src, int ld, int tid) {
#pragma unroll
    for (int it = 0; it < 2; it++) {
        int idx = tid + it * 256;          // 512 float4s total
        int k  = idx >> 5;
        int n4 = (idx & 31) << 2;
        *(float4*)(Ts + k * TS + n4) = *(const float4*)(src + (size_t)k * ld + n4);
    }
}

__device__ __forceinline__ void mm16(const float* As, const float* Bs,
                                     float acc[8][8], int ty, int tx) {
#pragma unroll
    for (int k = 0; k < 16; k++) {
        float a[8], b[8];
        *(float4*)&a[0] = *(const float4*)(As + k * TS + ty * 8);
        *(float4*)&a[4] = *(const float4*)(As + k * TS + ty * 8 + 4);
        *(float4*)&b[0] = *(const float4*)(Bs + k * TS + tx * 8);
        *(float4*)&b[4] = *(const float4*)(Bs + k * TS + tx * 8 + 4);
#pragma unroll
        for (int i = 0; i < 8; i++)
#pragma unroll
            for (int j = 0; j < 8; j++)
                acc[i][j] += a[i] * b[j];
    }
}

// ---------------------------------------------------------------------------
// Kernel 1: fused 4-way projection GEMM  Y = X @ W^T + b
// grid = (32 n-tiles, 128 m-tiles, 4 projections); z: 0=Q 1=K1 2=K2 3=V
// Output written directly in [b][h][s][d] layout into g_scratch.
// ---------------------------------------------------------------------------
__global__ __launch_bounds__(256, 2) void proj_gemm(
    const float* __restrict__ X,
    const float* __restrict__ wq, const float* __restrict__ wk1, const float* __restrict__ wk2,
    const float* __restrict__ bq, const float* __restrict__ bk1, const float* __restrict__ bk2) {
    __shared__ float As[16 * TS];
    __shared__ float Bs[16 * TS];

    int tid = threadIdx.x;
    int tx = tid & 15, ty = tid >> 4;
    int z = blockIdx.z;

    const float* W  = (z == 0) ? wq : (z == 1) ? wk1 : (z == 2) ? wk2 : g_wv;
    const float* bb = (z == 0) ? bq : (z == 1) ? bk1 : (z == 2) ? bk2 : g_bv;

    int rbase = blockIdx.y * 128;   // token rows
    int cbase = blockIdx.x * 128;   // output feature cols

    float acc[8][8];
#pragma unroll
    for (int i = 0; i < 8; i++)
#pragma unroll
        for (int j = 0; j < 8; j++) acc[i][j] = 0.f;

    for (int kt = 0; kt < HIDN / 16; kt++) {
        load_tileT(As, X + (size_t)rbase * HIDN + kt * 16, HIDN, tid);
        load_tileT(Bs, W + (size_t)cbase * HIDN + kt * 16, HIDN, tid);
        __syncthreads();
        mm16(As, Bs, acc, ty, tx);
        __syncthreads();
    }

    // Epilogue: bias + scatter into [b][h][s][d]
    int b  = rbase >> 8;
    int s0 = (rbase & 255);
    int h  = cbase >> 8;
    int d0 = (cbase & 255) + tx * 8;
    float4 bvA = *(const float4*)(bb + cbase + tx * 8);
    float4 bvB = *(const float4*)(bb + cbase + tx * 8 + 4);
    float* outp = g_scratch + (size_t)z * ((size_t)M_ * HIDN)
                + (size_t)(b * H_ + h) * (S_ * D_);
#pragma unroll
    for (int i = 0; i < 8; i++) {
        int s = s0 + ty * 8 + i;
        float4 o0 = make_float4(acc[i][0] + bvA.x, acc[i][1] + bvA.y,
                                acc[i][2] + bvA.z, acc[i][3] + bvA.w);
        float4 o1 = make_float4(acc[i][4] + bvB.x, acc[i][5] + bvB.y,
                                acc[i][6] + bvB.z, acc[i][7] + bvB.w);
        *(float4*)(outp + (size_t)s * D_ + d0)     = o0;
        *(float4*)(outp + (size_t)s * D_ + d0 + 4) = o1;
    }
}

// ---------------------------------------------------------------------------
// Kernel 2: attention per (b, h, q-half). All three chained GEMMs on-chip.
//   s1     = q @ k1^T                (128 x 256)
//   scores = (s1 @ k2^T) * SCALE     (128 x 256), cols >= 192 masked
//   P      = softmax(scores[:, :192])
//   ctx    = P @ V[0:192, :]         (128 x 256)
// Dynamic smem: P(128x256) + SC(128x128) + As + Bs = 213504 B
// ---------------------------------------------------------------------------
__global__ __launch_bounds__(256) void attn_kernel(float* __restrict__ out) {
    extern __shared__ float sm[];
    float* P  = sm;                        // 32768 floats
    float* SC = sm + 32768;                // 16384 floats
    float* As = sm + 32768 + 16384;        // 16*TS
    float* Bs = As + 16 * TS;              // 16*TS

    int tid = threadIdx.x;
    int tx = tid & 15, ty = tid >> 4;
    int qh = blockIdx.x;                   // q-half (0/1)
    int h  = blockIdx.y;
    int b  = blockIdx.z;
    int bh = b * H_ + h;

    const float* Qp  = g_scratch + (size_t)bh * (S_ * D_);
    const float* K1p = Qp + (size_t)1 * M_ * HIDN;
    const float* K2p = Qp + (size_t)2 * M_ * HIDN;
    const float* Vp  = Qp + (size_t)3 * M_ * HIDN;
    const float* Qt  = Qp + (size_t)(qh * 128) * D_;

    float acc[8][8];

    // ---- phase 1: s1 = q @ k1^T -> P ----
    for (int jh = 0; jh < 2; jh++) {
#pragma unroll
        for (int i = 0; i < 8; i++)
#pragma unroll
            for (int j = 0; j < 8; j++) acc[i][j] = 0.f;
        for (int kt = 0; kt < 16; kt++) {
            load_tileT(As, Qt + kt * 16, D_, tid);
            load_tileT(Bs, K1p + (size_t)(jh * 128) * D_ + kt * 16, D_, tid);
            __syncthreads();
            mm16(As, Bs, acc, ty, tx);
            __syncthreads();
        }
#pragma unroll
        for (int i = 0; i < 8; i++) {
            *(float4*)(P + (ty * 8 + i) * 256 + jh * 128 + tx * 8)     = *(float4*)&acc[i][0];
            *(float4*)(P + (ty * 8 + i) * 256 + jh * 128 + tx * 8 + 4) = *(float4*)&acc[i][4];
        }
        __syncthreads();
    }

    // ---- phase 1b: scores = (s1 @ k2^T) * SCALE ----
    for (int jh = 0; jh < 2; jh++) {
#pragma unroll
        for (int i = 0; i < 8; i++)
#pragma unroll
            for (int j = 0; j < 8; j++) acc[i][j] = 0.f;
        for (int kt = 0; kt < 16; kt++) {
            load_tileT(As, P + kt * 16, 256, tid);           // A = s1 (smem)
            load_tileT(Bs, K2p + (size_t)(jh * 128) * D_ + kt * 16, D_, tid);
            __syncthreads();
            mm16(As, Bs, acc, ty, tx);
            __syncthreads();
        }
        if (jh == 0) {
            // stash half 0 in SC (s1 still needed for half 1)
#pragma unroll
            for (int i = 0; i < 8; i++) {
                float4 o0 = make_float4(acc[i][0] * SCALE_, acc[i][1] * SCALE_,
                                        acc[i][2] * SCALE_, acc[i][3] * SCALE_);
                float4 o1 = make_float4(acc[i][4] * SCALE_, acc[i][5] * SCALE_,
                                        acc[i][6] * SCALE_, acc[i][7] * SCALE_);
                *(float4*)(SC + (ty * 8 + i) * 128 + tx * 8)     = o0;
                *(float4*)(SC + (ty * 8 + i) * 128 + tx * 8 + 4) = o1;
            }
            __syncthreads();
        } else {
            // half 1 straight into P right half (s1 reads are all done)
#pragma unroll
            for (int i = 0; i < 8; i++) {
                float4 o0 = make_float4(acc[i][0] * SCALE_, acc[i][1] * SCALE_,
                                        acc[i][2] * SCALE_, acc[i][3] * SCALE_);
                float4 o1 = make_float4(acc[i][4] * SCALE_, acc[i][5] * SCALE_,
                                        acc[i][6] * SCALE_, acc[i][7] * SCALE_);
                *(float4*)(P + (ty * 8 + i) * 256 + 128 + tx * 8)     = o0;
                *(float4*)(P + (ty * 8 + i) * 256 + 128 + tx * 8 + 4) = o1;
            }
        }
    }
    // copy SC -> P left half (disjoint from right-half writes above)
#pragma unroll
    for (int it = 0; it < 16; it++) {
        int idx = tid + it * 256;                   // 4096 float4s
        int row = idx >> 5;
        int c4  = (idx & 31) << 2;
        *(float4*)(P + row * 256 + c4) = *(float4*)(SC + row * 128 + c4);
    }
    __syncthreads();

    // ---- phase 2: row softmax over cols [0, 192) ----
    {
        int warp = tid >> 5, lane = tid & 31;
        for (int q = warp; q < 128; q += 8) {
            float* row = P + q * 256;
            float m = -1e30f;
#pragma unroll
            for (int c = 0; c < 6; c++) m = fmaxf(m, row[lane + c * 32]);
#pragma unroll
            for (int o = 16; o; o >>= 1) m = fmaxf(m, __shfl_xor_sync(0xffffffffu, m, o));
            float e[6];
            float ssum = 0.f;
#pragma unroll
            for (int c = 0; c < 6; c++) { e[c] = expf(row[lane + c * 32] - m); ssum += e[c]; }
#pragma unroll
            for (int o = 16; o; o >>= 1) ssum += __shfl_xor_sync(0xffffffffu, ssum, o);
            float inv = 1.f / ssum;
#pragma unroll
            for (int c = 0; c < 6; c++) row[lane + c * 32] = e[c] * inv;
        }
    }
    __syncthreads();

    // ---- phase 3: ctx = P[:, 0:192] @ V[0:192, :] ----
    for (int dh = 0; dh < 2; dh++) {
#pragma unroll
        for (int i = 0; i < 8; i++)
#pragma unroll
            for (int j = 0; j < 8; j++) acc[i][j] = 0.f;
        for (int kt = 0; kt < 12; kt++) {          // K = 192
            load_tileT(As, P + kt * 16, 256, tid); // A = probs (smem)
            load_tileN(Bs, Vp + (size_t)(kt * 16) * D_ + dh * 128, D_, tid);
            __syncthreads();
            mm16(As, Bs, acc, ty, tx);
            __syncthreads();
        }
        // write out[b][s][h*256 + d]
#pragma unroll
        for (int i = 0; i < 8; i++) {
            int s = qh * 128 + ty * 8 + i;
            int d = dh * 128 + tx * 8;
            float* op = out + ((size_t)(b * S_ + s)) * HIDN + h * D_ + d;
            *(float4*)op       = *(float4*)&acc[i][0];
            *(float4*)(op + 4) = *(float4*)&acc[i][4];
        }
    }
}

// ---------------------------------------------------------------------------
// Launch
// ---------------------------------------------------------------------------
extern "C" void kernel_launch(void* const* d_in, const int* in_sizes, int n_in,
                              void* d_out, int out_size) {
    const float* X   = (const float*)d_in[0];
    const float* wq  = (const float*)d_in[1];
    const float* bq  = (const float*)d_in[2];
    const float* wk1 = (const float*)d_in[3];
    const float* bk1 = (const float*)d_in[4];
    const float* wk2 = (const float*)d_in[5];
    const float* bk2 = (const float*)d_in[6];
    const float* wv1 = (const float*)d_in[7];
    const float* bv1 = (const float*)d_in[8];
    const float* wv2 = (const float*)d_in[9];
    const float* bv2 = (const float*)d_in[10];
    float* out = (float*)d_out;

    const int attn_smem = (32768 + 16384 + 2 * 16 * TS) * 4;   // 213504 B
    cudaFuncSetAttribute(attn_kernel, cudaFuncAttributeMaxDynamicSharedMemorySize, attn_smem);

    combine_wv<<<(HIDN * HIDN) / 256, 256>>>(wv1, wv2, bv1, bv2);

    dim3 gproj(HIDN / 128, M_ / 128, 4);     // (32, 128, 4)
    proj_gemm<<<gproj, 256>>>(X, wq, wk1, wk2, bq, bk1, bk2);

    dim3 gattn(2, H_, B_);                   // (q-half, head, batch)
    attn_kernel<<<gattn, 256, attn_smem>>>(out);
}

// round 7
// speedup vs baseline: 2.4759x; 2.4759x over previous
#include <cuda_runtime.h>
#include <cuda_bf16.h>
#include <cstdint>
#include <cstddef>

#define B_    64
#define S_    256
#define H_    16
#define D_    256
#define HIDN  4096
#define M_    (B_*S_)
#define SCALE_ 0.0625f
#define TS 132

__device__ float g_scratch[(size_t)4 * M_ * HIDN];
__device__ float g_wv[(size_t)HIDN * HIDN];
__device__ float g_bv[HIDN];
__device__ __nv_bfloat16 g_xhi[(size_t)M_ * HIDN];
__device__ __nv_bfloat16 g_xlo[(size_t)M_ * HIDN];
__device__ __nv_bfloat16 g_whi[(size_t)4 * HIDN * HIDN];
__device__ __nv_bfloat16 g_wlo[(size_t)4 * HIDN * HIDN];

__device__ __forceinline__ uint32_t smem_u32(const void* p) {
    uint32_t a;
    asm("{ .reg .u64 t; cvta.to.shared.u64 t, %1; cvt.u32.u64 %0, t; }" : "=r"(a) : "l"(p));
    return a;
}
__device__ __forceinline__ void cp16(uint32_t d, const void* s) {
    asm volatile("cp.async.cg.shared.global [%0], [%1], 16;" :: "r"(d), "l"(s) : "memory");
}
#define CP_COMMIT() asm volatile("cp.async.commit_group;" ::: "memory")
#define CP_WAIT1()  asm volatile("cp.async.wait_group 1;" ::: "memory")

__device__ __forceinline__ void ldsm4(uint32_t* r, uint32_t addr) {
    asm volatile("ldmatrix.sync.aligned.m8n8.x4.shared.b16 {%0,%1,%2,%3}, [%4];"
        : "=r"(r[0]), "=r"(r[1]), "=r"(r[2]), "=r"(r[3]) : "r"(addr));
}
__device__ __forceinline__ void mma16816(float* c, const uint32_t* a, uint32_t b0, uint32_t b1) {
    asm volatile("mma.sync.aligned.m16n8k16.row.col.f32.bf16.bf16.f32 "
        "{%0,%1,%2,%3}, {%4,%5,%6,%7}, {%8,%9}, {%0,%1,%2,%3};"
        : "+f"(c[0]), "+f"(c[1]), "+f"(c[2]), "+f"(c[3])
        : "r"(a[0]), "r"(a[1]), "r"(a[2]), "r"(a[3]), "r"(b0), "r"(b1));
}

__global__ void combine_wv(const float* __restrict__ wv1, const float* __restrict__ wv2,
                           const float* __restrict__ bv1, const float* __restrict__ bv2) {
    size_t i = (size_t)blockIdx.x * blockDim.x + threadIdx.x;
    if (i < (size_t)HIDN * HIDN) g_wv[i] = wv1[i] + wv2[i];
    if (i < HIDN)                g_bv[i] = bv1[i] + bv2[i];
}

struct alignas(8) BF4 { __nv_bfloat16 v[4]; };
__global__ void split4(const float* __restrict__ src, __nv_bfloat16* __restrict__ hi,
                       __nv_bfloat16* __restrict__ lo, int n4) {
    int i = blockIdx.x * blockDim.x + threadIdx.x;
    if (i >= n4) return;
    float4 x = ((const float4*)src)[i];
    float a[4] = {x.x, x.y, x.z, x.w};
    BF4 hb, lb;
#pragma unroll
    for (int j = 0; j < 4; j++) {
        __nv_bfloat16 h = __float2bfloat16_rn(a[j]);
        hb.v[j] = h;
        lb.v[j] = __float2bfloat16_rn(a[j] - __bfloat162float(h));
    }
    ((BF4*)hi)[i] = hb;
    ((BF4*)lo)[i] = lb;
}

// ---------------------------------------------------------------------------
// Projection GEMM via mma.sync, bf16x3 split, fp32 accum.
// grid = (nt=32, mt=128, z=4), 256 threads, CTA tile 128x128, warp tile 64x32.
// Smem per stage: Ahi/Alo/Bhi/Blo each 128 rows x 64B (K=32 bf16) = 32 KB;
// 2 stages = 64 KB. Swizzle: off ^ (((off>>6)&3)<<4) on 16B granules.
// ---------------------------------------------------------------------------
__global__ __launch_bounds__(256, 2) void proj_mma(
    const float* __restrict__ bq, const float* __restrict__ bk1, const float* __restrict__ bk2) {
    extern __shared__ char rawsm[];
    uint32_t sb = smem_u32(rawsm);

    int tid = threadIdx.x;
    int lane = tid & 31, wid = tid >> 5;
    int wm = wid & 1, wn = wid >> 1;          // warp grid 2(M) x 4(N)
    int nt = blockIdx.x, mt = blockIdx.y, z = blockIdx.z;
    int rbase = mt * 128, cbase = nt * 128;

    // --- precompute cp.async src/dst (8 chunks of 16B per thread per stage) ---
    const char* srcp[8];
    uint32_t    dst0[8];
#pragma unroll
    for (int i = 0; i < 8; i++) {
        int sidx = tid + i * 256;             // 0..2047
        int region = sidx >> 9;               // 0 Ahi 1 Alo 2 Bhi 3 Blo
        int idx = sidx & 511;
        int row = idx >> 2, c16 = idx & 3;
        const __nv_bfloat16* base; size_t rg;
        if (region == 0)      { base = g_xhi; rg = (size_t)(rbase + row); }
        else if (region == 1) { base = g_xlo; rg = (size_t)(rbase + row); }
        else if (region == 2) { base = g_whi; rg = (size_t)z * HIDN + cbase + row; }
        else                  { base = g_wlo; rg = (size_t)z * HIDN + cbase + row; }
        srcp[i] = (const char*)(base + rg * HIDN) + c16 * 16;
        dst0[i] = sb + (uint32_t)region * 8192u + (uint32_t)row * 64u
                + (uint32_t)((c16 ^ (row & 3)) << 4);
    }

    float acc[4][4][4];
#pragma unroll
    for (int a = 0; a < 4; a++)
#pragma unroll
        for (int b = 0; b < 4; b++)
#pragma unroll
            for (int c = 0; c < 4; c++) acc[a][b][c] = 0.f;

    // ldmatrix per-lane address components
    int arow = lane & 15, asel = lane >> 4;                 // A: 16 rows x 2 k-halves
    int brow = ((lane >> 3) & 1) * 8 + (lane & 7);          // B: n-pair rows
    int bsel = lane >> 4;

    // prologue: stage 0 -> buf 0
#pragma unroll
    for (int i = 0; i < 8; i++) cp16(dst0[i], srcp[i]);
    CP_COMMIT();

    for (int kt = 0; kt < 128; kt++) {
        if (kt + 1 < 128) {
            uint32_t bo = (uint32_t)((kt + 1) & 1) * 32768u;
            size_t ko = (size_t)(kt + 1) * 64;
#pragma unroll
            for (int i = 0; i < 8; i++) cp16(dst0[i] + bo, srcp[i] + ko);
        }
        CP_COMMIT();
        CP_WAIT1();
        __syncthreads();

        uint32_t sbuf = sb + (uint32_t)(kt & 1) * 32768u;
#pragma unroll
        for (int kk = 0; kk < 2; kk++) {
            uint32_t Bh[2][4], Bl[2][4];
#pragma unroll
            for (int p = 0; p < 2; p++) {
                int r = wn * 32 + p * 16 + brow;
                int c = kk * 2 + bsel;
                uint32_t off = (uint32_t)r * 64u + (uint32_t)((c ^ (r & 3)) << 4);
                ldsm4(Bh[p], sbuf + 16384u + off);
                ldsm4(Bl[p], sbuf + 24576u + off);
            }
#pragma unroll
            for (int tm = 0; tm < 4; tm++) {
                int r = wm * 64 + tm * 16 + arow;
                int c = kk * 2 + asel;
                uint32_t off = (uint32_t)r * 64u + (uint32_t)((c ^ (r & 3)) << 4);
                uint32_t Ah[4], Al[4];
                ldsm4(Ah, sbuf + off);
                ldsm4(Al, sbuf + 8192u + off);
#pragma unroll
                for (int tn = 0; tn < 4; tn++) {
                    int p = tn >> 1, j = tn & 1;
                    mma16816(acc[tm][tn], Ah, Bh[p][j], Bh[p][2 + j]);
                    mma16816(acc[tm][tn], Ah, Bl[p][j], Bl[p][2 + j]);
                    mma16816(acc[tm][tn], Al, Bh[p][j], Bh[p][2 + j]);
                }
            }
        }
        __syncthreads();
    }

    // epilogue: + bias, scatter to g_scratch [z][b][h][s][d]
    const float* bb = (z == 0) ? bq : (z == 1) ? bk1 : (z == 2) ? bk2 : g_bv;
    float* zbase = g_scratch + (size_t)z * ((size_t)M_ * HIDN);
#pragma unroll
    for (int tn = 0; tn < 4; tn++) {
        int cg = cbase + wn * 32 + tn * 8 + (lane & 3) * 2;   // global feature
        int h = cg >> 8, d = cg & 255;
        float b0 = bb[cg], b1 = bb[cg + 1];
#pragma unroll
        for (int tm = 0; tm < 4; tm++) {
#pragma unroll
            for (int half = 0; half < 2; half++) {
                int m = rbase + wm * 64 + tm * 16 + (lane >> 2) + half * 8;
                int bb_ = m >> 8, s = m & 255;
                float2 v = make_float2(acc[tm][tn][half * 2 + 0] + b0,
                                       acc[tm][tn][half * 2 + 1] + b1);
                *(float2*)(zbase + (((size_t)bb_ * H_ + h) * S_ + s) * D_ + d) = v;
            }
        }
    }
}

// --------------------------- fp32 SIMT attention (proven) -------------------
__device__ __forceinline__ void load_tileT(float* Ts, const float* src, int ld, int tid) {
#pragma unroll
    for (int it = 0; it < 2; it++) {
        int idx = tid + it * 256;
        int row = idx >> 2, k4 = (idx & 3) << 2;
        float4 v = *(const float4*)(src + (size_t)row * ld + k4);
        Ts[(k4+0)*TS+row] = v.x; Ts[(k4+1)*TS+row] = v.y;
        Ts[(k4+2)*TS+row] = v.z; Ts[(k4+3)*TS+row] = v.w;
    }
}
__device__ __forceinline__ void load_tileN(float* Ts, const float* src, int ld, int tid) {
#pragma unroll
    for (int it = 0; it < 2; it++) {
        int idx = tid + it * 256;
        int k = idx >> 5, n4 = (idx & 31) << 2;
        *(float4*)(Ts + k * TS + n4) = *(const float4*)(src + (size_t)k * ld + n4);
    }
}
__device__ __forceinline__ void mm16(const float* As, const float* Bs,
                                     float acc[8][8], int ty, int tx) {
#pragma unroll
    for (int k = 0; k < 16; k++) {
        float a[8], b[8];
        *(float4*)&a[0] = *(const float4*)(As + k*TS + ty*8);
        *(float4*)&a[4] = *(const float4*)(As + k*TS + ty*8 + 4);
        *(float4*)&b[0] = *(const float4*)(Bs + k*TS + tx*8);
        *(float4*)&b[4] = *(const float4*)(Bs + k*TS + tx*8 + 4);
#pragma unroll
        for (int i = 0; i < 8; i++)
#pragma unroll
            for (int j = 0; j < 8; j++) acc[i][j] += a[i] * b[j];
    }
}

__global__ __launch_bounds__(256) void attn_kernel(float* __restrict__ out) {
    extern __shared__ float sm[];
    float* P  = sm;
    float* SC = sm + 32768;
    float* As = sm + 32768 + 16384;
    float* Bs = As + 16 * TS;

    int tid = threadIdx.x;
    int tx = tid & 15, ty = tid >> 4;
    int qh = blockIdx.x, h = blockIdx.y, b = blockIdx.z;
    int bh = b * H_ + h;

    const float* Qp  = g_scratch + (size_t)bh * (S_ * D_);
    const float* K1p = Qp + (size_t)1 * M_ * HIDN;
    const float* K2p = Qp + (size_t)2 * M_ * HIDN;
    const float* Vp  = Qp + (size_t)3 * M_ * HIDN;
    const float* Qt  = Qp + (size_t)(qh * 128) * D_;

    float acc[8][8];

    for (int jh = 0; jh < 2; jh++) {
#pragma unroll
        for (int i = 0; i < 8; i++)
#pragma unroll
            for (int j = 0; j < 8; j++) acc[i][j] = 0.f;
        for (int kt = 0; kt < 16; kt++) {
            load_tileT(As, Qt + kt * 16, D_, tid);
            load_tileT(Bs, K1p + (size_t)(jh * 128) * D_ + kt * 16, D_, tid);
            __syncthreads();
            mm16(As, Bs, acc, ty, tx);
            __syncthreads();
        }
#pragma unroll
        for (int i = 0; i < 8; i++) {
            *(float4*)(P + (ty*8+i)*256 + jh*128 + tx*8)     = *(float4*)&acc[i][0];
            *(float4*)(P + (ty*8+i)*256 + jh*128 + tx*8 + 4) = *(float4*)&acc[i][4];
        }
        __syncthreads();
    }

    for (int jh = 0; jh < 2; jh++) {
#pragma unroll
        for (int i = 0; i < 8; i++)
#pragma unroll
            for (int j = 0; j < 8; j++) acc[i][j] = 0.f;
        for (int kt = 0; kt < 16; kt++) {
            load_tileT(As, P + kt * 16, 256, tid);
            load_tileT(Bs, K2p + (size_t)(jh * 128) * D_ + kt * 16, D_, tid);
            __syncthreads();
            mm16(As, Bs, acc, ty, tx);
            __syncthreads();
        }
        float* dst = (jh == 0) ? (SC + (ty*8)*128 + tx*8) : (P + (ty*8)*256 + 128 + tx*8);
        int ldd = (jh == 0) ? 128 : 256;
#pragma unroll
        for (int i = 0; i < 8; i++) {
            float4 o0 = make_float4(acc[i][0]*SCALE_, acc[i][1]*SCALE_, acc[i][2]*SCALE_, acc[i][3]*SCALE_);
            float4 o1 = make_float4(acc[i][4]*SCALE_, acc[i][5]*SCALE_, acc[i][6]*SCALE_, acc[i][7]*SCALE_);
            *(float4*)(dst + i*ldd)     = o0;
            *(float4*)(dst + i*ldd + 4) = o1;
        }
        if (jh == 0) __syncthreads();
    }
#pragma unroll
    for (int it = 0; it < 16; it++) {
        int idx = tid + it * 256;
        int row = idx >> 5, c4 = (idx & 31) << 2;
        *(float4*)(P + row*256 + c4) = *(float4*)(SC + row*128 + c4);
    }
    __syncthreads();

    {
        int warp = tid >> 5, lane = tid & 31;
        for (int q = warp; q < 128; q += 8) {
            float* row = P + q * 256;
            float m = -1e30f;
#pragma unroll
            for (int c = 0; c < 6; c++) m = fmaxf(m, row[lane + c*32]);
#pragma unroll
            for (int o = 16; o; o >>= 1) m = fmaxf(m, __shfl_xor_sync(0xffffffffu, m, o));
            float e[6], ssum = 0.f;
#pragma unroll
            for (int c = 0; c < 6; c++) { e[c] = expf(row[lane + c*32] - m); ssum += e[c]; }
#pragma unroll
            for (int o = 16; o; o >>= 1) ssum += __shfl_xor_sync(0xffffffffu, ssum, o);
            float inv = 1.f / ssum;
#pragma unroll
            for (int c = 0; c < 6; c++) row[lane + c*32] = e[c] * inv;
        }
    }
    __syncthreads();

    for (int dh = 0; dh < 2; dh++) {
#pragma unroll
        for (int i = 0; i < 8; i++)
#pragma unroll
            for (int j = 0; j < 8; j++) acc[i][j] = 0.f;
        for (int kt = 0; kt < 12; kt++) {
            load_tileT(As, P + kt * 16, 256, tid);
            load_tileN(Bs, Vp + (size_t)(kt * 16) * D_ + dh * 128, D_, tid);
            __syncthreads();
            mm16(As, Bs, acc, ty, tx);
            __syncthreads();
        }
#pragma unroll
        for (int i = 0; i < 8; i++) {
            int s = qh * 128 + ty * 8 + i;
            int d = dh * 128 + tx * 8;
            float* op = out + ((size_t)(b * S_ + s)) * HIDN + h * D_ + d;
            *(float4*)op       = *(float4*)&acc[i][0];
            *(float4*)(op + 4) = *(float4*)&acc[i][4];
        }
    }
}

extern "C" void kernel_launch(void* const* d_in, const int* in_sizes, int n_in,
                              void* d_out, int out_size) {
    const float* X   = (const float*)d_in[0];
    const float* wq  = (const float*)d_in[1];
    const float* bq  = (const float*)d_in[2];
    const float* wk1 = (const float*)d_in[3];
    const float* bk1 = (const float*)d_in[4];
    const float* wk2 = (const float*)d_in[5];
    const float* bk2 = (const float*)d_in[6];
    const float* wv1 = (const float*)d_in[7];
    const float* bv1 = (const float*)d_in[8];
    const float* wv2 = (const float*)d_in[9];
    const float* bv2 = (const float*)d_in[10];
    float* out = (float*)d_out;

    static __nv_bfloat16 *whi = nullptr, *wlo = nullptr, *xhi = nullptr, *xlo = nullptr;
    static float* wvp = nullptr;
    if (!whi) {
        cudaGetSymbolAddress((void**)&whi, g_whi);
        cudaGetSymbolAddress((void**)&wlo, g_wlo);
        cudaGetSymbolAddress((void**)&wvp, g_wv);
        cudaGetSymbolAddress((void**)&xhi, g_xhi);
        cudaGetSymbolAddress((void**)&xlo, g_xlo);
    }

    combine_wv<<<(HIDN * HIDN) / 256, 256>>>(wv1, wv2, bv1, bv2);

    const int NW4 = (HIDN * HIDN) / 4;
    const int NX4 = (M_ * HIDN) / 4;
    split4<<<NX4 / 256, 256>>>(X,   xhi, xlo, NX4);
    split4<<<NW4 / 256, 256>>>(wq,  whi + (size_t)0 * HIDN * HIDN, wlo + (size_t)0 * HIDN * HIDN, NW4);
    split4<<<NW4 / 256, 256>>>(wk1, whi + (size_t)1 * HIDN * HIDN, wlo + (size_t)1 * HIDN * HIDN, NW4);
    split4<<<NW4 / 256, 256>>>(wk2, whi + (size_t)2 * HIDN * HIDN, wlo + (size_t)2 * HIDN * HIDN, NW4);
    split4<<<NW4 / 256, 256>>>(wvp, whi + (size_t)3 * HIDN * HIDN, wlo + (size_t)3 * HIDN * HIDN, NW4);

    const int proj_smem = 65536;
    cudaFuncSetAttribute(proj_mma, cudaFuncAttributeMaxDynamicSharedMemorySize, proj_smem);
    dim3 gproj(HIDN / 128, M_ / 128, 4);    // (32, 128, 4)
    proj_mma<<<gproj, 256, proj_smem>>>(bq, bk1, bk2);

    const int attn_smem = (32768 + 16384 + 2 * 16 * TS) * 4;
    cudaFuncSetAttribute(attn_kernel, cudaFuncAttributeMaxDynamicSharedMemorySize, attn_smem);
    dim3 gattn(2, H_, B_);
    attn_kernel<<<gattn, 256, attn_smem>>>(out);
}

// round 8
// speedup vs baseline: 2.7577x; 1.1138x over previous
#include <cuda_runtime.h>
#include <cuda_bf16.h>
#include <cstdint>
#include <cstddef>

#define B_    64
#define S_    256
#define H_    16
#define D_    256
#define HIDN  4096
#define M_    (B_*S_)
#define SCALE_ 0.0625f

// ---------------- device scratch ----------------
__device__ float g_wv[(size_t)HIDN * HIDN];
__device__ float g_bv[HIDN];
__device__ __nv_bfloat16 g_xhi[(size_t)M_ * HIDN];
__device__ __nv_bfloat16 g_xlo[(size_t)M_ * HIDN];
__device__ __nv_bfloat16 g_whi[(size_t)4 * HIDN * HIDN];
__device__ __nv_bfloat16 g_wlo[(size_t)4 * HIDN * HIDN];
// projections, bf16 split. Q/K1/K2: [b,h,s,d]; V transposed: [b,h,d,s]
__device__ __nv_bfloat16 g_qhi[(size_t)M_ * HIDN];
__device__ __nv_bfloat16 g_qlo[(size_t)M_ * HIDN];
__device__ __nv_bfloat16 g_k1hi[(size_t)M_ * HIDN];
__device__ __nv_bfloat16 g_k1lo[(size_t)M_ * HIDN];
__device__ __nv_bfloat16 g_k2hi[(size_t)M_ * HIDN];
__device__ __nv_bfloat16 g_k2lo[(size_t)M_ * HIDN];
__device__ __nv_bfloat16 g_vthi[(size_t)M_ * HIDN];
__device__ __nv_bfloat16 g_vtlo[(size_t)M_ * HIDN];

__device__ __forceinline__ uint32_t smem_u32(const void* p) {
    uint32_t a;
    asm("{ .reg .u64 t; cvta.to.shared.u64 t, %1; cvt.u32.u64 %0, t; }" : "=r"(a) : "l"(p));
    return a;
}
__device__ __forceinline__ void cp16(uint32_t d, const void* s) {
    asm volatile("cp.async.cg.shared.global [%0], [%1], 16;" :: "r"(d), "l"(s) : "memory");
}
#define CP_COMMIT() asm volatile("cp.async.commit_group;" ::: "memory")
#define CP_WAIT1()  asm volatile("cp.async.wait_group 1;" ::: "memory")

__device__ __forceinline__ void ldsm4(uint32_t* r, uint32_t addr) {
    asm volatile("ldmatrix.sync.aligned.m8n8.x4.shared.b16 {%0,%1,%2,%3}, [%4];"
        : "=r"(r[0]), "=r"(r[1]), "=r"(r[2]), "=r"(r[3]) : "r"(addr));
}
__device__ __forceinline__ void mma16816(float* c, const uint32_t* a, uint32_t b0, uint32_t b1) {
    asm volatile("mma.sync.aligned.m16n8k16.row.col.f32.bf16.bf16.f32 "
        "{%0,%1,%2,%3}, {%4,%5,%6,%7}, {%8,%9}, {%0,%1,%2,%3};"
        : "+f"(c[0]), "+f"(c[1]), "+f"(c[2]), "+f"(c[3])
        : "r"(a[0]), "r"(a[1]), "r"(a[2]), "r"(a[3]), "r"(b0), "r"(b1));
}
__device__ __forceinline__ uint32_t pack_bf2(float x, float y) {
    __nv_bfloat16 hx = __float2bfloat16_rn(x), hy = __float2bfloat16_rn(y);
    return (uint32_t)__bfloat16_as_ushort(hx) | ((uint32_t)__bfloat16_as_ushort(hy) << 16);
}

__global__ void combine_wv(const float* __restrict__ wv1, const float* __restrict__ wv2,
                           const float* __restrict__ bv1, const float* __restrict__ bv2) {
    size_t i = (size_t)blockIdx.x * blockDim.x + threadIdx.x;
    if (i < (size_t)HIDN * HIDN) g_wv[i] = wv1[i] + wv2[i];
    if (i < HIDN)                g_bv[i] = bv1[i] + bv2[i];
}

struct alignas(8) BF4 { __nv_bfloat16 v[4]; };
__global__ void split4(const float* __restrict__ src, __nv_bfloat16* __restrict__ hi,
                       __nv_bfloat16* __restrict__ lo, int n4) {
    int i = blockIdx.x * blockDim.x + threadIdx.x;
    if (i >= n4) return;
    float4 x = ((const float4*)src)[i];
    float a[4] = {x.x, x.y, x.z, x.w};
    BF4 hb, lb;
#pragma unroll
    for (int j = 0; j < 4; j++) {
        __nv_bfloat16 h = __float2bfloat16_rn(a[j]);
        hb.v[j] = h;
        lb.v[j] = __float2bfloat16_rn(a[j] - __bfloat162float(h));
    }
    ((BF4*)hi)[i] = hb;
    ((BF4*)lo)[i] = lb;
}

// ---------------------------------------------------------------------------
// Projection GEMM (mainloop identical to the passing R7 kernel).
// Epilogue now adds bias and writes bf16 hi/lo; V goes out transposed.
// ---------------------------------------------------------------------------
__global__ __launch_bounds__(256, 2) void proj_mma(
    const float* __restrict__ bq, const float* __restrict__ bk1, const float* __restrict__ bk2) {
    extern __shared__ char rawsm[];
    uint32_t sb = smem_u32(rawsm);

    int tid = threadIdx.x;
    int lane = tid & 31, wid = tid >> 5;
    int wm = wid & 1, wn = wid >> 1;
    int nt = blockIdx.x, mt = blockIdx.y, z = blockIdx.z;
    int rbase = mt * 128, cbase = nt * 128;

    const char* srcp[8];
    uint32_t    dst0[8];
#pragma unroll
    for (int i = 0; i < 8; i++) {
        int sidx = tid + i * 256;
        int region = sidx >> 9;
        int idx = sidx & 511;
        int row = idx >> 2, c16 = idx & 3;
        const __nv_bfloat16* base; size_t rg;
        if (region == 0)      { base = g_xhi; rg = (size_t)(rbase + row); }
        else if (region == 1) { base = g_xlo; rg = (size_t)(rbase + row); }
        else if (region == 2) { base = g_whi; rg = (size_t)z * HIDN + cbase + row; }
        else                  { base = g_wlo; rg = (size_t)z * HIDN + cbase + row; }
        srcp[i] = (const char*)(base + rg * HIDN) + c16 * 16;
        dst0[i] = sb + (uint32_t)region * 8192u + (uint32_t)row * 64u
                + (uint32_t)((c16 ^ (row & 3)) << 4);
    }

    float acc[4][4][4];
#pragma unroll
    for (int a = 0; a < 4; a++)
#pragma unroll
        for (int b = 0; b < 4; b++)
#pragma unroll
            for (int c = 0; c < 4; c++) acc[a][b][c] = 0.f;

    int arow = lane & 15, asel = lane >> 4;
    int brow = ((lane >> 3) & 1) * 8 + (lane & 7);
    int bsel = lane >> 4;

#pragma unroll
    for (int i = 0; i < 8; i++) cp16(dst0[i], srcp[i]);
    CP_COMMIT();

    for (int kt = 0; kt < 128; kt++) {
        if (kt + 1 < 128) {
            uint32_t bo = (uint32_t)((kt + 1) & 1) * 32768u;
            size_t ko = (size_t)(kt + 1) * 64;
#pragma unroll
            for (int i = 0; i < 8; i++) cp16(dst0[i] + bo, srcp[i] + ko);
        }
        CP_COMMIT();
        CP_WAIT1();
        __syncthreads();

        uint32_t sbuf = sb + (uint32_t)(kt & 1) * 32768u;
#pragma unroll
        for (int kk = 0; kk < 2; kk++) {
            uint32_t Bh[2][4], Bl[2][4];
#pragma unroll
            for (int p = 0; p < 2; p++) {
                int r = wn * 32 + p * 16 + brow;
                int c = kk * 2 + bsel;
                uint32_t off = (uint32_t)r * 64u + (uint32_t)((c ^ (r & 3)) << 4);
                ldsm4(Bh[p], sbuf + 16384u + off);
                ldsm4(Bl[p], sbuf + 24576u + off);
            }
#pragma unroll
            for (int tm = 0; tm < 4; tm++) {
                int r = wm * 64 + tm * 16 + arow;
                int c = kk * 2 + asel;
                uint32_t off = (uint32_t)r * 64u + (uint32_t)((c ^ (r & 3)) << 4);
                uint32_t Ah[4], Al[4];
                ldsm4(Ah, sbuf + off);
                ldsm4(Al, sbuf + 8192u + off);
#pragma unroll
                for (int tn = 0; tn < 4; tn++) {
                    int p = tn >> 1, j = tn & 1;
                    mma16816(acc[tm][tn], Ah, Bh[p][j], Bh[p][2 + j]);
                    mma16816(acc[tm][tn], Ah, Bl[p][j], Bl[p][2 + j]);
                    mma16816(acc[tm][tn], Al, Bh[p][j], Bh[p][2 + j]);
                }
            }
        }
        __syncthreads();
    }

    // epilogue: + bias, split -> bf16 hi/lo
    const float* bb = (z == 0) ? bq : (z == 1) ? bk1 : (z == 2) ? bk2 : g_bv;
    __nv_bfloat16* ohi = (z == 0) ? g_qhi : (z == 1) ? g_k1hi : (z == 2) ? g_k2hi : g_vthi;
    __nv_bfloat16* olo = (z == 0) ? g_qlo : (z == 1) ? g_k1lo : (z == 2) ? g_k2lo : g_vtlo;
#pragma unroll
    for (int tn = 0; tn < 4; tn++) {
        int cg = cbase + wn * 32 + tn * 8 + (lane & 3) * 2;
        int h = cg >> 8, d = cg & 255;
        float b0 = bb[cg], b1 = bb[cg + 1];
#pragma unroll
        for (int tm = 0; tm < 4; tm++) {
#pragma unroll
            for (int half = 0; half < 2; half++) {
                int m = rbase + wm * 64 + tm * 16 + (lane >> 2) + half * 8;
                int bb_ = m >> 8, s = m & 255;
                float v0 = acc[tm][tn][half * 2 + 0] + b0;
                float v1 = acc[tm][tn][half * 2 + 1] + b1;
                __nv_bfloat16 h0 = __float2bfloat16_rn(v0);
                __nv_bfloat16 h1 = __float2bfloat16_rn(v1);
                __nv_bfloat16 l0 = __float2bfloat16_rn(v0 - __bfloat162float(h0));
                __nv_bfloat16 l1 = __float2bfloat16_rn(v1 - __bfloat162float(h1));
                if (z < 3) {
                    size_t idx = (((size_t)bb_ * H_ + h) * S_ + s) * D_ + d;
                    *(uint32_t*)(ohi + idx) = (uint32_t)__bfloat16_as_ushort(h0)
                                            | ((uint32_t)__bfloat16_as_ushort(h1) << 16);
                    *(uint32_t*)(olo + idx) = (uint32_t)__bfloat16_as_ushort(l0)
                                            | ((uint32_t)__bfloat16_as_ushort(l1) << 16);
                } else {  // V transposed: [b,h,d,s]
                    size_t base = ((size_t)bb_ * H_ + h) * (S_ * D_) + s;
                    ohi[base + (size_t)d * S_]       = h0;
                    ohi[base + (size_t)(d + 1) * S_] = h1;
                    olo[base + (size_t)d * S_]       = l0;
                    olo[base + (size_t)(d + 1) * S_] = l1;
                }
            }
        }
    }
}

// ---------------------------------------------------------------------------
// Attention via mma.sync, bf16x3 split everywhere, fp32 accum + softmax.
// Grid (qb=4, H, B), 256 threads (8 warps, 2x4), CTA tile 64 q-rows.
// ---------------------------------------------------------------------------
#define SB_OFF   0u        // B staging: 2 stages x (hi 16KB + lo 16KB) = 64 KB
#define SA_OFF   65536u    // A staging: 2 stages x (hi 4KB + lo 4KB) = 16 KB
#define S1HI_OFF 81920u    // 64 x 264 bf16 = 33792 B
#define S1LO_OFF 115712u   // 33792 B
#define SCR_OFF  81920u    // alias after s1 dead: 64 x 192 f32 = 49152 B
#define PHI_OFF  149504u   // 64 x 200 bf16 = 25600 B
#define PLO_OFF  175104u   // 25600 B
#define ATTN_SMEM 200704

__global__ __launch_bounds__(256, 1) void attn_mma(float* __restrict__ out) {
    extern __shared__ char sm[];
    uint32_t sb = smem_u32(sm);
    int tid = threadIdx.x, lane = tid & 31, wid = tid >> 5;
    int wm = wid & 1, wn = wid >> 1;
    int qb = blockIdx.x, h = blockIdx.y, b = blockIdx.z;
    int bh = b * H_ + h;
    size_t bho = (size_t)bh * (S_ * D_);

    const __nv_bfloat16* Qh  = g_qhi  + bho; const __nv_bfloat16* Ql  = g_qlo  + bho;
    const __nv_bfloat16* K1h = g_k1hi + bho; const __nv_bfloat16* K1l = g_k1lo + bho;
    const __nv_bfloat16* K2h = g_k2hi + bho; const __nv_bfloat16* K2l = g_k2lo + bho;
    const __nv_bfloat16* Vh  = g_vthi + bho; const __nv_bfloat16* Vl  = g_vtlo + bho;

    int arow = lane & 15, asel = lane >> 4;
    int brow = ((lane >> 3) & 1) * 8 + (lane & 7);
    int bsel = lane >> 4;

    float acc[2][8][4];

    // ---- staging helpers (inline) ----
    // B256: 2048 chunks (8/thr); B192: 1536 (6/thr); A64: 512 (2/thr)
#define STAGE_B256(HP, LP, st, kt) do { \
    _Pragma("unroll") \
    for (int i = 0; i < 8; i++) { \
        int sidx = tid + i * 256; \
        int reg = sidx >> 10, idx = sidx & 1023; \
        int row = idx >> 2, c16 = idx & 3; \
        const __nv_bfloat16* s_ = (reg ? (LP) : (HP)) + (size_t)row * 256 + (kt) * 32 + c16 * 8; \
        uint32_t d_ = sb + SB_OFF + (uint32_t)(st) * 32768u + (uint32_t)reg * 16384u \
                    + (uint32_t)row * 64u + (uint32_t)((c16 ^ (row & 3)) << 4); \
        cp16(d_, s_); \
    } } while (0)

#define STAGE_B192(HP, LP, st, kt) do { \
    _Pragma("unroll") \
    for (int i = 0; i < 6; i++) { \
        int sidx = tid + i * 256; \
        int reg = sidx >= 768 ? 1 : 0; \
        int idx = sidx - reg * 768; \
        int row = idx >> 2, c16 = idx & 3; \
        const __nv_bfloat16* s_ = (reg ? (LP) : (HP)) + (size_t)row * 256 + (kt) * 32 + c16 * 8; \
        uint32_t d_ = sb + SB_OFF + (uint32_t)(st) * 32768u + (uint32_t)reg * 16384u \
                    + (uint32_t)row * 64u + (uint32_t)((c16 ^ (row & 3)) << 4); \
        cp16(d_, s_); \
    } } while (0)

#define STAGE_A64(HP, LP, st, kt) do { \
    _Pragma("unroll") \
    for (int i = 0; i < 2; i++) { \
        int sidx = tid + i * 256; \
        int reg = sidx >> 8, idx = sidx & 255; \
        int row = idx >> 2, c16 = idx & 3; \
        const __nv_bfloat16* s_ = (reg ? (LP) : (HP)) + (size_t)(qb * 64 + row) * 256 + (kt) * 32 + c16 * 8; \
        uint32_t d_ = sb + SA_OFF + (uint32_t)(st) * 8192u + (uint32_t)reg * 4096u \
                    + (uint32_t)row * 64u + (uint32_t)((c16 ^ (row & 3)) << 4); \
        cp16(d_, s_); \
    } } while (0)

    // load B fragments (hi+lo) for 4 n-groups from staged buffer
#define LOAD_B(Bh, Bl, bufB, kk) do { \
    _Pragma("unroll") \
    for (int ng = 0; ng < 4; ng++) { \
        int r_ = wn * 64 + ng * 16 + brow; \
        int c_ = (kk) * 2 + bsel; \
        uint32_t off_ = (uint32_t)r_ * 64u + (uint32_t)((c_ ^ (r_ & 3)) << 4); \
        ldsm4(Bh[ng], (bufB) + off_); \
        ldsm4(Bl[ng], (bufB) + 16384u + off_); \
    } } while (0)

#define DO_MMAS(Bh, Bl, Ah, Al) do { \
    _Pragma("unroll") \
    for (int tm = 0; tm < 2; tm++) \
    _Pragma("unroll") \
    for (int ng = 0; ng < 4; ng++) \
    _Pragma("unroll") \
    for (int j = 0; j < 2; j++) { \
        int tn = ng * 2 + j; \
        mma16816(acc[tm][tn], Ah[tm], Bh[ng][j], Bh[ng][2 + j]); \
        mma16816(acc[tm][tn], Ah[tm], Bl[ng][j], Bl[ng][2 + j]); \
        mma16816(acc[tm][tn], Al[tm], Bh[ng][j], Bh[ng][2 + j]); \
    } } while (0)

    // ================= phase 1: s1 = Q @ K1^T =================
#pragma unroll
    for (int a = 0; a < 2; a++)
#pragma unroll
        for (int b2 = 0; b2 < 8; b2++)
#pragma unroll
            for (int c = 0; c < 4; c++) acc[a][b2][c] = 0.f;

    STAGE_B256(K1h, K1l, 0, 0);
    STAGE_A64(Qh, Ql, 0, 0);
    CP_COMMIT();
    for (int kt = 0; kt < 8; kt++) {
        if (kt + 1 < 8) {
            STAGE_B256(K1h, K1l, (kt + 1) & 1, kt + 1);
            STAGE_A64(Qh, Ql, (kt + 1) & 1, kt + 1);
        }
        CP_COMMIT(); CP_WAIT1(); __syncthreads();
        uint32_t bufB = sb + SB_OFF + (uint32_t)(kt & 1) * 32768u;
        uint32_t bufA = sb + SA_OFF + (uint32_t)(kt & 1) * 8192u;
#pragma unroll
        for (int kk = 0; kk < 2; kk++) {
            uint32_t Bh[4][4], Bl[4][4], Ah[2][4], Al[2][4];
            LOAD_B(Bh, Bl, bufB, kk);
#pragma unroll
            for (int tm = 0; tm < 2; tm++) {
                int r = wm * 32 + tm * 16 + arow;
                int c = kk * 2 + asel;
                uint32_t off = (uint32_t)r * 64u + (uint32_t)((c ^ (r & 3)) << 4);
                ldsm4(Ah[tm], bufA + off);
                ldsm4(Al[tm], bufA + 4096u + off);
            }
            DO_MMAS(Bh, Bl, Ah, Al);
        }
        __syncthreads();
    }
    // epilogue: split s1 -> smem bf16 (row stride 264 bf16 = 528 B)
#pragma unroll
    for (int tm = 0; tm < 2; tm++)
#pragma unroll
        for (int tn = 0; tn < 8; tn++)
#pragma unroll
            for (int half = 0; half < 2; half++) {
                int m = wm * 32 + tm * 16 + (lane >> 2) + half * 8;
                int n = wn * 64 + tn * 8 + (lane & 3) * 2;
                float v0 = acc[tm][tn][half * 2 + 0];
                float v1 = acc[tm][tn][half * 2 + 1];
                __nv_bfloat16 h0 = __float2bfloat16_rn(v0), h1 = __float2bfloat16_rn(v1);
                float l0 = v0 - __bfloat162float(h0), l1 = v1 - __bfloat162float(h1);
                *(uint32_t*)(sm + S1HI_OFF + m * 528 + n * 2) =
                    (uint32_t)__bfloat16_as_ushort(h0) | ((uint32_t)__bfloat16_as_ushort(h1) << 16);
                *(uint32_t*)(sm + S1LO_OFF + m * 528 + n * 2) = pack_bf2(l0, l1);
            }
    __syncthreads();

    // ================= phase 2: scores(:, :192) = s1 @ K2^T * SCALE =================
#pragma unroll
    for (int a = 0; a < 2; a++)
#pragma unroll
        for (int b2 = 0; b2 < 8; b2++)
#pragma unroll
            for (int c = 0; c < 4; c++) acc[a][b2][c] = 0.f;

    STAGE_B192(K2h, K2l, 0, 0);
    CP_COMMIT();
    for (int kt = 0; kt < 8; kt++) {
        if (kt + 1 < 8) STAGE_B192(K2h, K2l, (kt + 1) & 1, kt + 1);
        CP_COMMIT(); CP_WAIT1(); __syncthreads();
        if (wn < 3) {
            uint32_t bufB = sb + SB_OFF + (uint32_t)(kt & 1) * 32768u;
#pragma unroll
            for (int kk = 0; kk < 2; kk++) {
                uint32_t Bh[4][4], Bl[4][4], Ah[2][4], Al[2][4];
                LOAD_B(Bh, Bl, bufB, kk);
#pragma unroll
                for (int tm = 0; tm < 2; tm++) {
                    int r = wm * 32 + tm * 16 + arow;
                    uint32_t co = (uint32_t)(kt * 32 + kk * 16 + asel * 8) * 2u;
                    ldsm4(Ah[tm], sb + S1HI_OFF + (uint32_t)r * 528u + co);
                    ldsm4(Al[tm], sb + S1LO_OFF + (uint32_t)r * 528u + co);
                }
                DO_MMAS(Bh, Bl, Ah, Al);
            }
        }
        __syncthreads();
    }
    // epilogue: scores fp32 into SCR (stride 192 floats), only wn<3
    if (wn < 3) {
#pragma unroll
        for (int tm = 0; tm < 2; tm++)
#pragma unroll
            for (int tn = 0; tn < 8; tn++)
#pragma unroll
                for (int half = 0; half < 2; half++) {
                    int m = wm * 32 + tm * 16 + (lane >> 2) + half * 8;
                    int n = wn * 64 + tn * 8 + (lane & 3) * 2;
                    float2 v = make_float2(acc[tm][tn][half * 2 + 0] * SCALE_,
                                           acc[tm][tn][half * 2 + 1] * SCALE_);
                    *(float2*)(sm + SCR_OFF + m * 768 + n * 4) = v;
                }
    }
    __syncthreads();

    // ================= softmax over 192 cols, split P -> bf16 hi/lo =================
    {
#pragma unroll
        for (int i = 0; i < 8; i++) {
            int r = wid * 8 + i;
            const float* row = (const float*)(sm + SCR_OFF + r * 768);
            float mx = -1e30f;
#pragma unroll
            for (int c = 0; c < 6; c++) mx = fmaxf(mx, row[lane + c * 32]);
#pragma unroll
            for (int o = 16; o; o >>= 1) mx = fmaxf(mx, __shfl_xor_sync(0xffffffffu, mx, o));
            float e[6], ssum = 0.f;
#pragma unroll
            for (int c = 0; c < 6; c++) { e[c] = expf(row[lane + c * 32] - mx); ssum += e[c]; }
#pragma unroll
            for (int o = 16; o; o >>= 1) ssum += __shfl_xor_sync(0xffffffffu, ssum, o);
            float inv = 1.f / ssum;
#pragma unroll
            for (int c = 0; c < 6; c++) {
                float p = e[c] * inv;
                __nv_bfloat16 ph = __float2bfloat16_rn(p);
                __nv_bfloat16 pl = __float2bfloat16_rn(p - __bfloat162float(ph));
                int col = lane + c * 32;
                *(__nv_bfloat16*)(sm + PHI_OFF + r * 400 + col * 2) = ph;
                *(__nv_bfloat16*)(sm + PLO_OFF + r * 400 + col * 2) = pl;
            }
        }
    }
    __syncthreads();

    // ================= phase 3: ctx = P[:, :192] @ V^T =================
#pragma unroll
    for (int a = 0; a < 2; a++)
#pragma unroll
        for (int b2 = 0; b2 < 8; b2++)
#pragma unroll
            for (int c = 0; c < 4; c++) acc[a][b2][c] = 0.f;

    STAGE_B256(Vh, Vl, 0, 0);
    CP_COMMIT();
    for (int kt = 0; kt < 6; kt++) {                // K = 192
        if (kt + 1 < 6) STAGE_B256(Vh, Vl, (kt + 1) & 1, kt + 1);
        CP_COMMIT(); CP_WAIT1(); __syncthreads();
        uint32_t bufB = sb + SB_OFF + (uint32_t)(kt & 1) * 32768u;
#pragma unroll
        for (int kk = 0; kk < 2; kk++) {
            uint32_t Bh[4][4], Bl[4][4], Ah[2][4], Al[2][4];
            LOAD_B(Bh, Bl, bufB, kk);
#pragma unroll
            for (int tm = 0; tm < 2; tm++) {
                int r = wm * 32 + tm * 16 + arow;
                uint32_t co = (uint32_t)(kt * 32 + kk * 16 + asel * 8) * 2u;
                ldsm4(Ah[tm], sb + PHI_OFF + (uint32_t)r * 400u + co);
                ldsm4(Al[tm], sb + PLO_OFF + (uint32_t)r * 400u + co);
            }
            DO_MMAS(Bh, Bl, Ah, Al);
        }
        __syncthreads();
    }
    // epilogue: out[b, s, h*256 + d]
#pragma unroll
    for (int tm = 0; tm < 2; tm++)
#pragma unroll
        for (int tn = 0; tn < 8; tn++)
#pragma unroll
            for (int half = 0; half < 2; half++) {
                int m = wm * 32 + tm * 16 + (lane >> 2) + half * 8;
                int n = wn * 64 + tn * 8 + (lane & 3) * 2;
                int s = qb * 64 + m;
                float2 v = make_float2(acc[tm][tn][half * 2 + 0], acc[tm][tn][half * 2 + 1]);
                *(float2*)(out + ((size_t)(b * S_ + s)) * HIDN + h * D_ + n) = v;
            }
}

extern "C" void kernel_launch(void* const* d_in, const int* in_sizes, int n_in,
                              void* d_out, int out_size) {
    const float* X   = (const float*)d_in[0];
    const float* wq  = (const float*)d_in[1];
    const float* bq  = (const float*)d_in[2];
    const float* wk1 = (const float*)d_in[3];
    const float* bk1 = (const float*)d_in[4];
    const float* wk2 = (const float*)d_in[5];
    const float* bk2 = (const float*)d_in[6];
    const float* wv1 = (const float*)d_in[7];
    const float* bv1 = (const float*)d_in[8];
    const float* wv2 = (const float*)d_in[9];
    const float* bv2 = (const float*)d_in[10];
    float* out = (float*)d_out;

    static __nv_bfloat16 *whi = nullptr, *wlo = nullptr, *xhi = nullptr, *xlo = nullptr;
    static float* wvp = nullptr;
    if (!whi) {
        cudaGetSymbolAddress((void**)&whi, g_whi);
        cudaGetSymbolAddress((void**)&wlo, g_wlo);
        cudaGetSymbolAddress((void**)&wvp, g_wv);
        cudaGetSymbolAddress((void**)&xhi, g_xhi);
        cudaGetSymbolAddress((void**)&xlo, g_xlo);
    }

    combine_wv<<<(HIDN * HIDN) / 256, 256>>>(wv1, wv2, bv1, bv2);

    const int NW4 = (HIDN * HIDN) / 4;
    const int NX4 = (M_ * HIDN) / 4;
    split4<<<NX4 / 256, 256>>>(X,   xhi, xlo, NX4);
    split4<<<NW4 / 256, 256>>>(wq,  whi + (size_t)0 * HIDN * HIDN, wlo + (size_t)0 * HIDN * HIDN, NW4);
    split4<<<NW4 / 256, 256>>>(wk1, whi + (size_t)1 * HIDN * HIDN, wlo + (size_t)1 * HIDN * HIDN, NW4);
    split4<<<NW4 / 256, 256>>>(wk2, whi + (size_t)2 * HIDN * HIDN, wlo + (size_t)2 * HIDN * HIDN, NW4);
    split4<<<NW4 / 256, 256>>>(wvp, whi + (size_t)3 * HIDN * HIDN, wlo + (size_t)3 * HIDN * HIDN, NW4);

    const int proj_smem = 65536;
    cudaFuncSetAttribute(proj_mma, cudaFuncAttributeMaxDynamicSharedMemorySize, proj_smem);
    dim3 gproj(HIDN / 128, M_ / 128, 4);
    proj_mma<<<gproj, 256, proj_smem>>>(bq, bk1, bk2);

    cudaFuncSetAttribute(attn_mma, cudaFuncAttributeMaxDynamicSharedMemorySize, ATTN_SMEM);
    dim3 gattn(4, H_, B_);
    attn_mma<<<gattn, 256, ATTN_SMEM>>>(out);
}